// round 16
// baseline (speedup 1.0000x reference)
#include <cuda_runtime.h>
#include <math.h>

#define Bsz 32
#define Cc  384
#define Nn  4096
#define Ee  256
#define NHn 16
#define HIDn 128
#define NODES (Bsz*NHn)   // 512

typedef unsigned long long u64;

// ---------------- scratch (device globals; no allocation allowed) ----------
__device__ __align__(16) float g_xm[Bsz*Cc];
__device__ __align__(16) float g_qk[Bsz*Cc*NHn];          // [b][c][h], pre-scaled 1/sqrt(HD)
__device__ __align__(16) float g_bq[Bsz*NHn];
__device__ __align__(16) float g_attT[(size_t)Bsz*NHn*Nn]; // exp(logits), [b][h][n]
__device__ __align__(16) float g_S[Bsz*48];               // per b: [sum|sum*x|sum*y][16h]
__device__ __align__(16) float g_pooled[Bsz*Cc*NHn];      // UNNORMALIZED, layout [b][c][h]
__device__ __align__(16) float g_values[NODES*Ee];
__device__ __align__(16) float g_vm[NODES*HIDn];
__device__ __align__(16) float g_agg[NODES*HIDn];

// ---------------- f32x2 helpers --------------------------------------------
__device__ __forceinline__ void fma2(u64 &d, u64 a, u64 b) {
    asm("fma.rn.f32x2 %0, %1, %2, %0;" : "+l"(d) : "l"(a), "l"(b));
}
__device__ __forceinline__ u64 pk2(float a, float b) {
    u64 r; asm("mov.b64 %0, {%1, %2};" : "=l"(r) : "f"(a), "f"(b)); return r;
}
__device__ __forceinline__ float2 unpk(u64 v) {
    float2 r; asm("mov.b64 {%0, %1}, %2;" : "=f"(r.x), "=f"(r.y) : "l"(v)); return r;
}
__device__ __forceinline__ void redv4(float* p, float a, float b, float c, float d) {
    asm volatile("red.global.add.v4.f32 [%0], {%1,%2,%3,%4};"
                 :: "l"(p), "f"(a), "f"(b), "f"(c), "f"(d) : "memory");
}

// ---------------- pass 1: xm[b,c] = mean_n x[b,c,n] (warp-per-row) ---------
__global__ void mean_kernel(const float* __restrict__ x) {
    int b = blockIdx.y;
    int c = blockIdx.x*8 + (threadIdx.x >> 5);
    int lane = threadIdx.x & 31;
    const float4* xr = (const float4*)(x + ((size_t)b*Cc + c)*Nn) + lane;
    float s0 = 0.f, s1 = 0.f, s2 = 0.f, s3 = 0.f;
    #pragma unroll 8
    for (int step = 0; step < 32; step++) {
        float4 v = xr[step*32];
        s0 += v.x; s1 += v.y; s2 += v.z; s3 += v.w;
    }
    float s = (s0 + s1) + (s2 + s3);
    #pragma unroll
    for (int o = 16; o > 0; o >>= 1) s += __shfl_xor_sync(0xffffffffu, s, o);
    if (lane == 0) g_xm[b*Cc + c] = s * (1.0f/(float)Nn);
}

// ---------------- zero scratch accumulators --------------------------------
__global__ void zero_kernel() {
    int i = blockIdx.x*256 + threadIdx.x;
    const int T1 = Bsz*Cc*NHn, T2 = T1 + NODES*HIDn, T3 = T2 + Bsz*48;
    for (; i < T3; i += gridDim.x*256) {
        if (i < T1)      g_pooled[i] = 0.f;
        else if (i < T2) g_agg[i - T1] = 0.f;
        else             g_S[i - T2] = 0.f;
    }
}

// ---------------- fused q + qk, split by head-group ------------------------
__global__ void qq_kernel(const float* __restrict__ qw, const float* __restrict__ qb,
                          const float* __restrict__ kw, const float* __restrict__ kb) {
    int hg = blockIdx.x, b = blockIdx.y, tid = threadIdx.x;
    __shared__ __align__(16) float xs[Cc];
    __shared__ __align__(16) float qs[64];
    xs[tid] = g_xm[b*Cc + tid];
    __syncthreads();
    if (tid < 64) {
        int e = hg*64 + tid;
        const float4* w4 = (const float4*)(qw + (size_t)e*Cc);
        const float4* x4 = (const float4*)xs;
        float acc = qb[e];
        #pragma unroll 8
        for (int c4 = 0; c4 < Cc/4; c4++) {
            float4 w = w4[c4], xv = x4[c4];
            acc += w.x*xv.x + w.y*xv.y + w.z*xv.z + w.w*xv.w;
        }
        qs[tid] = acc;
    }
    __syncthreads();
    int c = tid;
    #pragma unroll
    for (int hl = 0; hl < 4; hl++) {
        float s = 0.f;
        const float* kr = kw + (size_t)(hg*64 + hl*16)*Cc + c;
        #pragma unroll
        for (int d = 0; d < 16; d++) s = fmaf(qs[hl*16 + d], kr[(size_t)d*Cc], s);
        g_qk[((size_t)b*Cc + c)*NHn + hg*4 + hl] = 0.25f * s;
    }
    if (tid < 4) {
        float s = 0.f;
        #pragma unroll
        for (int d = 0; d < 16; d++) s += qs[tid*16 + d] * kb[hg*64 + tid*16 + d];
        g_bq[b*NHn + hg*4 + tid] = 0.25f * s;
    }
}

// ---------------- FUSED logits + exp + S-sums (R14 proven) -----------------
// grid (Nn/256, Bsz) = 512 blocks, block 256. Full 384-c dot per block.
__global__ void __launch_bounds__(256) logits_kernel(const float* __restrict__ x) {
    int b = blockIdx.y;
    int tid = threadIdx.x;
    int hh = tid >> 7;           // h-half (0/1)
    int np = tid & 127;          // n-pair index
    int n0 = blockIdx.x*256 + np*2;

    __shared__ __align__(16) float4 qks[Cc*4];     // 24KB: [c][h/4]
    __shared__ __align__(16) float2 exs[NHn][128]; // 16KB: [h][n-pair]
    __shared__ float bqs[NHn];
    const float4* qkg = (const float4*)(g_qk + (size_t)b*Cc*NHn);
    for (int i = tid; i < Cc*4; i += 256) qks[i] = qkg[i];
    if (tid < NHn) bqs[tid] = g_bq[b*NHn + tid];
    __syncthreads();

    u64 acc[8];
    #pragma unroll
    for (int h = 0; h < 8; h++) acc[h] = 0ull;

    const float* xb = x + (size_t)b*Cc*Nn + n0;
    float2 buf[8];
    #pragma unroll
    for (int j = 0; j < 8; j++) buf[j] = __ldg((const float2*)(xb + (size_t)j*Nn));

    #pragma unroll 8
    for (int c = 0; c < Cc; c++) {
        float2 xv = buf[c & 7];
        if (c + 8 < Cc) buf[c & 7] = __ldg((const float2*)(xb + (size_t)(c+8)*Nn));
        u64 xp = pk2(xv.x, xv.y);
        float4 q0 = qks[c*4 + hh*2], q1 = qks[c*4 + hh*2 + 1];
        fma2(acc[0], xp, pk2(q0.x, q0.x)); fma2(acc[1], xp, pk2(q0.y, q0.y));
        fma2(acc[2], xp, pk2(q0.z, q0.z)); fma2(acc[3], xp, pk2(q0.w, q0.w));
        fma2(acc[4], xp, pk2(q1.x, q1.x)); fma2(acc[5], xp, pk2(q1.y, q1.y));
        fma2(acc[6], xp, pk2(q1.z, q1.z)); fma2(acc[7], xp, pk2(q1.w, q1.w));
    }

    float* dstT = g_attT + (size_t)b*NHn*Nn + (size_t)hh*8*Nn + n0;
    #pragma unroll
    for (int h = 0; h < 8; h++) {
        float2 v = unpk(acc[h]);
        float bq = bqs[hh*8 + h];
        float e0 = __expf(v.x + bq), e1 = __expf(v.y + bq);
        *(float2*)(dstT + (size_t)h*Nn) = make_float2(e0, e1);
        exs[hh*8 + h][np] = make_float2(e0, e1);
    }
    __syncthreads();

    {
        int h = tid >> 4, seg = tid & 15, lane = tid & 31;
        int ng0 = blockIdx.x*256 + seg*16;
        float sm = 0.f, sx = 0.f, sy = 0.f;
        #pragma unroll
        for (int j = 0; j < 8; j++) {
            float2 e = exs[h][seg*8 + j];
            int ng = ng0 + j*2;
            sm += e.x + e.y;
            sx += e.x*(float)(ng>>6)  + e.y*(float)((ng+1)>>6);
            sy += e.x*(float)(ng&63)  + e.y*(float)((ng+1)&63);
        }
        #pragma unroll
        for (int o = 1; o < 16; o <<= 1) {
            sm += __shfl_xor_sync(0xffffffffu, sm, o);
            sx += __shfl_xor_sync(0xffffffffu, sx, o);
            sy += __shfl_xor_sync(0xffffffffu, sy, o);
        }
        if ((lane & 15) == 0) {
            atomicAdd(&g_S[b*48      + h], sm);
            atomicAdd(&g_S[b*48 + 16 + h], sx);
            atomicAdd(&g_S[b*48 + 32 + h], sy);
        }
    }
}

// ---------------- pool (UNNORMALIZED): pooled[b][c][h] += sum_n ex*x -------
// grid (2 cgroup, 32 nsplit, Bsz) = 2048 blocks, block 256 (8 warps).
// 128-n exs stage (8KB); attT read 2x chip-wide (was 4x).
__global__ void pool_kernel(const float* __restrict__ x) {
    int cg = blockIdx.x, s = blockIdx.y, b = blockIdx.z;
    int tid = threadIdx.x, w = tid >> 5, lane = tid & 31;
    int c_sub = lane >> 3, nq = lane & 7;

    __shared__ __align__(16) float ex_s[16][128];  // 8KB, [h][n]
    const float* srcT = g_attT + (size_t)b*NHn*Nn + s*128;
    for (int i = tid; i < 16*32; i += 256) {
        int h = i >> 5, j = i & 31;
        ((float4*)ex_s[h])[j] = ((const float4*)(srcT + (size_t)h*Nn))[j];
    }
    __syncthreads();

    #pragma unroll
    for (int g = 0; g < 6; g++) {
        int c = cg*192 + g*32 + w*4 + c_sub;
        const float* xrow = x + ((size_t)b*Cc + c)*Nn + s*128;
        u64 acc[16];
        #pragma unroll
        for (int h = 0; h < 16; h++) acc[h] = 0ull;

        #pragma unroll
        for (int step = 0; step < 4; step++) {
            int n0 = step*32 + nq*4;
            float4 xv = *(const float4*)(xrow + n0);
            u64 xp0 = pk2(xv.x, xv.y), xp1 = pk2(xv.z, xv.w);
            #pragma unroll
            for (int h = 0; h < 16; h++) {
                ulonglong2 e2 = *(const ulonglong2*)&ex_s[h][n0];
                fma2(acc[h], xp0, e2.x);
                fma2(acc[h], xp1, e2.y);
            }
        }
        float pv[16];
        #pragma unroll
        for (int h = 0; h < 16; h++) {
            float2 v2 = unpk(acc[h]);
            float sv = v2.x + v2.y;
            sv += __shfl_xor_sync(0xffffffffu, sv, 1);
            sv += __shfl_xor_sync(0xffffffffu, sv, 2);
            sv += __shfl_xor_sync(0xffffffffu, sv, 4);
            pv[h] = sv;
        }
        if (nq == 0) {
            float* dst = g_pooled + ((size_t)b*Cc + c)*NHn;
            redv4(dst +  0, pv[0],  pv[1],  pv[2],  pv[3]);
            redv4(dst +  4, pv[4],  pv[5],  pv[6],  pv[7]);
            redv4(dst +  8, pv[8],  pv[9],  pv[10], pv[11]);
            redv4(dst + 12, pv[12], pv[13], pv[14], pv[15]);
        }
    }
}

// ---------------- fused values + vm (4 nodes/block, same b) ----------------
// inv computed inline from g_S (no fin kernel).
__global__ void values_vm_kernel(const float* __restrict__ vw, const float* __restrict__ vb,
                                 const float* __restrict__ msg_w, const float* __restrict__ msg_b) {
    int n0 = blockIdx.x * 4;        // nodes n0..n0+3: b = n0>>4, h0 = n0&15
    int b = n0 >> 4, h0 = n0 & 15;
    int tid = threadIdx.x; // 256
    __shared__ __align__(16) float ps[4*Cc];
    __shared__ __align__(16) float vs[4*Ee];
    float i0 = 1.0f/g_S[b*48 + h0],     i1 = 1.0f/g_S[b*48 + h0 + 1];
    float i2 = 1.0f/g_S[b*48 + h0 + 2], i3 = 1.0f/g_S[b*48 + h0 + 3];
    for (int c = tid; c < Cc; c += 256) {
        float4 v = *(const float4*)(g_pooled + ((size_t)b*Cc + c)*NHn + h0);
        ps[0*Cc + c] = v.x*i0; ps[1*Cc + c] = v.y*i1; ps[2*Cc + c] = v.z*i2; ps[3*Cc + c] = v.w*i3;
    }
    __syncthreads();
    {
        int e = tid;
        float bias = vb[e];
        float acc[4];
        #pragma unroll
        for (int i = 0; i < 4; i++) acc[i] = bias;
        const float4* w4 = (const float4*)(vw + (size_t)e*Cc);
        #pragma unroll 2
        for (int c4 = 0; c4 < Cc/4; c4++) {
            float4 wv = w4[c4];
            #pragma unroll
            for (int i = 0; i < 4; i++) {
                float4 a = ((const float4*)(ps + i*Cc))[c4];
                acc[i] += wv.x*a.x + wv.y*a.y + wv.z*a.z + wv.w*a.w;
            }
        }
        #pragma unroll
        for (int i = 0; i < 4; i++) {
            vs[i*Ee + e] = acc[i];
            g_values[(size_t)(n0+i)*Ee + e] = acc[i];
        }
    }
    __syncthreads();
    for (int t = tid; t < 4*HIDn; t += 256) {
        int i = t >> 7, j = t & 127;
        float acc = msg_b[j];
        const float4* w4 = (const float4*)(msg_w + (size_t)j*Ee);
        const float4* v4 = (const float4*)(vs + i*Ee);
        #pragma unroll 4
        for (int k4 = 0; k4 < Ee/4; k4++) {
            float4 wv = w4[k4], a = v4[k4];
            acc += wv.x*a.x + wv.y*a.y + wv.z*a.z + wv.w*a.w;
        }
        g_vm[(size_t)(n0+i)*HIDn + j] = acc;
    }
}

// ---------------- edge kernel: RFF + gate + gather + segment mean ----------
// Positions computed inline from g_S (no fin / g_pos).
__global__ void edge_kernel(const int* __restrict__ esrc, const int* __restrict__ edst,
                            const float* __restrict__ brff, const float* __restrict__ embw,
                            int EG) {
    int e0  = blockIdx.x * 8;
    int tid = threadIdx.x; // 128
    __shared__ int   ssrc[8], sdst[8];
    __shared__ float srel[8][2];
    __shared__ __align__(16) float ea[8][64];

    if (tid < 8) {
        int idx = e0 + tid;
        int s_ = (idx < EG) ? esrc[idx] : 0;
        int d_ = (idx < EG) ? edst[idx] : 0;
        ssrc[tid] = s_; sdst[tid] = d_;
        int sb = s_ >> 4, sh = s_ & 15, db = d_ >> 4, dh = d_ & 15;
        float is = 1.0f/g_S[sb*48 + sh], id = 1.0f/g_S[db*48 + dh];
        srel[tid][0] = g_S[sb*48 + 16 + sh]*is - g_S[db*48 + 16 + dh]*id;
        srel[tid][1] = g_S[sb*48 + 32 + sh]*is - g_S[db*48 + 32 + dh]*id;
    }
    __syncthreads();
    if (tid < 32) {
        float b0 = brff[tid*2+0], b1 = brff[tid*2+1];
        #pragma unroll
        for (int e = 0; e < 8; e++) {
            float pj = srel[e][0]*b0 + srel[e][1]*b1;
            float sv, cv;
            __sincosf(pj, &sv, &cv);
            ea[e][tid]      = 1.41421356237f * sv;
            ea[e][tid + 32] = 1.41421356237f * cv;
        }
    }
    __syncthreads();

    float4 wr[16];
    const float4* wrow = (const float4*)(embw + (size_t)tid*64);
    #pragma unroll
    for (int i = 0; i < 16; i++) wr[i] = wrow[i];

    #pragma unroll
    for (int e = 0; e < 8; e++) {
        if (e0 + e >= EG) break;
        const float4* eav = (const float4*)ea[e];
        float g = 0.f;
        #pragma unroll
        for (int i = 0; i < 16; i++) {
            float4 a = eav[i];
            g += wr[i].x*a.x + wr[i].y*a.y + wr[i].z*a.z + wr[i].w*a.w;
        }
        float m = g_vm[(size_t)ssrc[e]*HIDn + tid] * g * (1.0f/15.0f);
        atomicAdd(&g_agg[(size_t)sdst[e]*HIDn + tid], m);
    }
}

// ---------------- final: silu MLP + layer scale + skip (4 nodes/block) -----
__global__ void final_kernel(const float* __restrict__ lin1_w, const float* __restrict__ lin1_b,
                             const float* __restrict__ lin2_w, const float* __restrict__ lin2_b,
                             const float* __restrict__ lscale, float* __restrict__ out) {
    int n0  = blockIdx.x * 4;
    int tid = threadIdx.x; // 256
    __shared__ __align__(16) float ag[4*HIDn];
    __shared__ __align__(16) float hs[4*512];
    for (int i = tid; i < 4*HIDn; i += 256) ag[i] = g_agg[(size_t)n0*HIDn + i];
    __syncthreads();

    for (int j = tid; j < 512; j += 256) {
        const float4* w4 = (const float4*)(lin1_w + (size_t)j*HIDn);
        float a0 = lin1_b[j], a1 = a0, a2 = a0, a3 = a0;
        const float4* g0 = (const float4*)(ag);
        const float4* g1 = (const float4*)(ag + HIDn);
        const float4* g2 = (const float4*)(ag + 2*HIDn);
        const float4* g3 = (const float4*)(ag + 3*HIDn);
        #pragma unroll 2
        for (int k4 = 0; k4 < HIDn/4; k4++) {
            float4 wv = w4[k4];
            float4 b0 = g0[k4], b1v = g1[k4], b2 = g2[k4], b3 = g3[k4];
            a0 += wv.x*b0.x + wv.y*b0.y + wv.z*b0.z + wv.w*b0.w;
            a1 += wv.x*b1v.x + wv.y*b1v.y + wv.z*b1v.z + wv.w*b1v.w;
            a2 += wv.x*b2.x + wv.y*b2.y + wv.z*b2.z + wv.w*b2.w;
            a3 += wv.x*b3.x + wv.y*b3.y + wv.z*b3.z + wv.w*b3.w;
        }
        hs[0*512 + j] = a0 / (1.f + __expf(-a0));
        hs[1*512 + j] = a1 / (1.f + __expf(-a1));
        hs[2*512 + j] = a2 / (1.f + __expf(-a2));
        hs[3*512 + j] = a3 / (1.f + __expf(-a3));
    }
    __syncthreads();

    int e = tid;
    const float4* w4 = (const float4*)(lin2_w + (size_t)e*512);
    float o0 = lin2_b[e], o1 = o0, o2 = o0, o3 = o0;
    const float4* h0 = (const float4*)(hs);
    const float4* h1 = (const float4*)(hs + 512);
    const float4* h2 = (const float4*)(hs + 1024);
    const float4* h3 = (const float4*)(hs + 1536);
    #pragma unroll 2
    for (int j4 = 0; j4 < 128; j4++) {
        float4 wv = w4[j4];
        float4 b0 = h0[j4], b1v = h1[j4], b2 = h2[j4], b3 = h3[j4];
        o0 += wv.x*b0.x + wv.y*b0.y + wv.z*b0.z + wv.w*b0.w;
        o1 += wv.x*b1v.x + wv.y*b1v.y + wv.z*b1v.z + wv.w*b1v.w;
        o2 += wv.x*b2.x + wv.y*b2.y + wv.z*b2.z + wv.w*b2.w;
        o3 += wv.x*b3.x + wv.y*b3.y + wv.z*b3.z + wv.w*b3.w;
    }
    float ls = lscale[e];
    out[(size_t)(n0+0)*Ee + e] = ls*o0 + g_values[(size_t)(n0+0)*Ee + e];
    out[(size_t)(n0+1)*Ee + e] = ls*o1 + g_values[(size_t)(n0+1)*Ee + e];
    out[(size_t)(n0+2)*Ee + e] = ls*o2 + g_values[(size_t)(n0+2)*Ee + e];
    out[(size_t)(n0+3)*Ee + e] = ls*o3 + g_values[(size_t)(n0+3)*Ee + e];
}

// ---------------------------------------------------------------------------
extern "C" void kernel_launch(void* const* d_in, const int* in_sizes, int n_in,
                              void* d_out, int out_size) {
    const float* x      = (const float*)d_in[0];
    const float* qw     = (const float*)d_in[1];
    const float* qb     = (const float*)d_in[2];
    const float* kw     = (const float*)d_in[3];
    const float* kb     = (const float*)d_in[4];
    const float* vw     = (const float*)d_in[5];
    const float* vb     = (const float*)d_in[6];
    const float* brff   = (const float*)d_in[7];
    const float* msg_w  = (const float*)d_in[8];
    const float* msg_b  = (const float*)d_in[9];
    const float* emb_w  = (const float*)d_in[10];
    const float* lin1_w = (const float*)d_in[11];
    const float* lin1_b = (const float*)d_in[12];
    const float* lin2_w = (const float*)d_in[13];
    const float* lin2_b = (const float*)d_in[14];
    const float* lsc    = (const float*)d_in[15];
    const int*   esrc   = (const int*)d_in[16];
    const int*   edst   = (const int*)d_in[17];
    int EG = in_sizes[16];
    float* out = (float*)d_out;

    zero_kernel     <<<256, 256>>>();
    mean_kernel     <<<dim3(Cc/8, Bsz), 256>>>(x);
    qq_kernel       <<<dim3(4, Bsz), Cc>>>(qw, qb, kw, kb);
    logits_kernel   <<<dim3(Nn/256, Bsz), 256>>>(x);
    pool_kernel     <<<dim3(2, 32, Bsz), 256>>>(x);
    values_vm_kernel<<<NODES/4, 256>>>(vw, vb, msg_w, msg_b);
    edge_kernel     <<<(EG + 7)/8, 128>>>(esrc, edst, brff, emb_w, EG);
    final_kernel    <<<NODES/4, 256>>>(lin1_w, lin1_b, lin2_w, lin2_b, lsc, out);
}

// round 17
// speedup vs baseline: 1.2077x; 1.2077x over previous
#include <cuda_runtime.h>
#include <math.h>

#define Bsz 32
#define Cc  384
#define Nn  4096
#define Ee  256
#define NHn 16
#define HIDn 128
#define NODES (Bsz*NHn)   // 512

typedef unsigned long long u64;

// ---------------- scratch (device globals; no allocation allowed) ----------
__device__ __align__(16) float g_xm[Bsz*Cc];
__device__ __align__(16) float g_qk[Bsz*Cc*NHn];          // [b][c][h], pre-scaled 1/sqrt(HD)
__device__ __align__(16) float g_bq[Bsz*NHn];
__device__ __align__(16) float g_attT[(size_t)Bsz*NHn*Nn]; // exp(logits), [b][h][n]
__device__ __align__(16) float g_S[Bsz*48];               // per b: [sum|sum*x|sum*y][16h]
__device__ __align__(16) float g_pooled[Bsz*Cc*NHn];      // UNNORMALIZED, layout [b][c][h]
__device__ __align__(16) float g_values[NODES*Ee];
__device__ __align__(16) float g_vm[NODES*HIDn];
__device__ __align__(16) float g_agg[NODES*HIDn];

// ---------------- f32x2 helpers --------------------------------------------
__device__ __forceinline__ void fma2(u64 &d, u64 a, u64 b) {
    asm("fma.rn.f32x2 %0, %1, %2, %0;" : "+l"(d) : "l"(a), "l"(b));
}
__device__ __forceinline__ u64 pk2(float a, float b) {
    u64 r; asm("mov.b64 %0, {%1, %2};" : "=l"(r) : "f"(a), "f"(b)); return r;
}
__device__ __forceinline__ float2 unpk(u64 v) {
    float2 r; asm("mov.b64 {%0, %1}, %2;" : "=f"(r.x), "=f"(r.y) : "l"(v)); return r;
}
__device__ __forceinline__ void redv4(float* p, float a, float b, float c, float d) {
    asm volatile("red.global.add.v4.f32 [%0], {%1,%2,%3,%4};"
                 :: "l"(p), "f"(a), "f"(b), "f"(c), "f"(d) : "memory");
}

// ---------------- pass 1: xm[b,c] = mean_n x[b,c,n] (warp-per-row) ---------
__global__ void mean_kernel(const float* __restrict__ x) {
    int b = blockIdx.y;
    int c = blockIdx.x*8 + (threadIdx.x >> 5);
    int lane = threadIdx.x & 31;
    const float4* xr = (const float4*)(x + ((size_t)b*Cc + c)*Nn) + lane;
    float s0 = 0.f, s1 = 0.f, s2 = 0.f, s3 = 0.f;
    #pragma unroll 8
    for (int step = 0; step < 32; step++) {
        float4 v = xr[step*32];
        s0 += v.x; s1 += v.y; s2 += v.z; s3 += v.w;
    }
    float s = (s0 + s1) + (s2 + s3);
    #pragma unroll
    for (int o = 16; o > 0; o >>= 1) s += __shfl_xor_sync(0xffffffffu, s, o);
    if (lane == 0) g_xm[b*Cc + c] = s * (1.0f/(float)Nn);
}

// ---------------- zero scratch accumulators --------------------------------
__global__ void zero_kernel() {
    int i = blockIdx.x*256 + threadIdx.x;
    const int T1 = Bsz*Cc*NHn, T2 = T1 + NODES*HIDn, T3 = T2 + Bsz*48;
    for (; i < T3; i += gridDim.x*256) {
        if (i < T1)      g_pooled[i] = 0.f;
        else if (i < T2) g_agg[i - T1] = 0.f;
        else             g_S[i - T2] = 0.f;
    }
}

// ---------------- fused q + qk, split by head-group ------------------------
__global__ void qq_kernel(const float* __restrict__ qw, const float* __restrict__ qb,
                          const float* __restrict__ kw, const float* __restrict__ kb) {
    int hg = blockIdx.x, b = blockIdx.y, tid = threadIdx.x;
    __shared__ __align__(16) float xs[Cc];
    __shared__ __align__(16) float qs[64];
    xs[tid] = g_xm[b*Cc + tid];
    __syncthreads();
    if (tid < 64) {
        int e = hg*64 + tid;
        const float4* w4 = (const float4*)(qw + (size_t)e*Cc);
        const float4* x4 = (const float4*)xs;
        float acc = qb[e];
        #pragma unroll 8
        for (int c4 = 0; c4 < Cc/4; c4++) {
            float4 w = w4[c4], xv = x4[c4];
            acc += w.x*xv.x + w.y*xv.y + w.z*xv.z + w.w*xv.w;
        }
        qs[tid] = acc;
    }
    __syncthreads();
    int c = tid;
    #pragma unroll
    for (int hl = 0; hl < 4; hl++) {
        float s = 0.f;
        const float* kr = kw + (size_t)(hg*64 + hl*16)*Cc + c;
        #pragma unroll
        for (int d = 0; d < 16; d++) s = fmaf(qs[hl*16 + d], kr[(size_t)d*Cc], s);
        g_qk[((size_t)b*Cc + c)*NHn + hg*4 + hl] = 0.25f * s;
    }
    if (tid < 4) {
        float s = 0.f;
        #pragma unroll
        for (int d = 0; d < 16; d++) s += qs[tid*16 + d] * kb[hg*64 + tid*16 + d];
        g_bq[b*NHn + hg*4 + tid] = 0.25f * s;
    }
}

// ---------------- FUSED logits + exp + S-sums (R14 proven) -----------------
// grid (Nn/256, Bsz) = 512 blocks, block 256. Full 384-c dot per block.
__global__ void __launch_bounds__(256) logits_kernel(const float* __restrict__ x) {
    int b = blockIdx.y;
    int tid = threadIdx.x;
    int hh = tid >> 7;           // h-half (0/1)
    int np = tid & 127;          // n-pair index
    int n0 = blockIdx.x*256 + np*2;

    __shared__ __align__(16) float4 qks[Cc*4];     // 24KB: [c][h/4]
    __shared__ __align__(16) float2 exs[NHn][128]; // 16KB: [h][n-pair]
    __shared__ float bqs[NHn];
    const float4* qkg = (const float4*)(g_qk + (size_t)b*Cc*NHn);
    for (int i = tid; i < Cc*4; i += 256) qks[i] = qkg[i];
    if (tid < NHn) bqs[tid] = g_bq[b*NHn + tid];
    __syncthreads();

    u64 acc[8];
    #pragma unroll
    for (int h = 0; h < 8; h++) acc[h] = 0ull;

    const float* xb = x + (size_t)b*Cc*Nn + n0;
    float2 buf[8];
    #pragma unroll
    for (int j = 0; j < 8; j++) buf[j] = __ldg((const float2*)(xb + (size_t)j*Nn));

    #pragma unroll 8
    for (int c = 0; c < Cc; c++) {
        float2 xv = buf[c & 7];
        if (c + 8 < Cc) buf[c & 7] = __ldg((const float2*)(xb + (size_t)(c+8)*Nn));
        u64 xp = pk2(xv.x, xv.y);
        float4 q0 = qks[c*4 + hh*2], q1 = qks[c*4 + hh*2 + 1];
        fma2(acc[0], xp, pk2(q0.x, q0.x)); fma2(acc[1], xp, pk2(q0.y, q0.y));
        fma2(acc[2], xp, pk2(q0.z, q0.z)); fma2(acc[3], xp, pk2(q0.w, q0.w));
        fma2(acc[4], xp, pk2(q1.x, q1.x)); fma2(acc[5], xp, pk2(q1.y, q1.y));
        fma2(acc[6], xp, pk2(q1.z, q1.z)); fma2(acc[7], xp, pk2(q1.w, q1.w));
    }

    float* dstT = g_attT + (size_t)b*NHn*Nn + (size_t)hh*8*Nn + n0;
    #pragma unroll
    for (int h = 0; h < 8; h++) {
        float2 v = unpk(acc[h]);
        float bq = bqs[hh*8 + h];
        float e0 = __expf(v.x + bq), e1 = __expf(v.y + bq);
        *(float2*)(dstT + (size_t)h*Nn) = make_float2(e0, e1);
        exs[hh*8 + h][np] = make_float2(e0, e1);
    }
    __syncthreads();

    {
        int h = tid >> 4, seg = tid & 15, lane = tid & 31;
        int ng0 = blockIdx.x*256 + seg*16;
        float sm = 0.f, sx = 0.f, sy = 0.f;
        #pragma unroll
        for (int j = 0; j < 8; j++) {
            float2 e = exs[h][seg*8 + j];
            int ng = ng0 + j*2;
            sm += e.x + e.y;
            sx += e.x*(float)(ng>>6)  + e.y*(float)((ng+1)>>6);
            sy += e.x*(float)(ng&63)  + e.y*(float)((ng+1)&63);
        }
        #pragma unroll
        for (int o = 1; o < 16; o <<= 1) {
            sm += __shfl_xor_sync(0xffffffffu, sm, o);
            sx += __shfl_xor_sync(0xffffffffu, sx, o);
            sy += __shfl_xor_sync(0xffffffffu, sy, o);
        }
        if ((lane & 15) == 0) {
            atomicAdd(&g_S[b*48      + h], sm);
            atomicAdd(&g_S[b*48 + 16 + h], sx);
            atomicAdd(&g_S[b*48 + 32 + h], sy);
        }
    }
}

// ---------------- pool (UNNORMALIZED): pooled[b][c][h] += sum_n ex*x -------
// grid (4 cgroup, 16 nsplit, Bsz), block 256 (8 warps).  [R14 verbatim]
__global__ void pool_kernel(const float* __restrict__ x) {
    int b = blockIdx.z, s = blockIdx.y, cg0 = blockIdx.x * 96;
    int tid = threadIdx.x, w = tid >> 5, lane = tid & 31;
    int c_sub = lane >> 3, nq = lane & 7;

    __shared__ __align__(16) float ex_s[16][256];  // 16KB, [h][n]
    const float* srcT = g_attT + (size_t)b*NHn*Nn + s*256;
    for (int i = tid; i < 16*64; i += 256) {
        int h = i >> 6, j = i & 63;
        ((float4*)ex_s[h])[j] = ((const float4*)(srcT + (size_t)h*Nn))[j];
    }
    __syncthreads();

    #pragma unroll
    for (int g = 0; g < 3; g++) {
        int c = cg0 + g*32 + w*4 + c_sub;
        const float* xrow = x + ((size_t)b*Cc + c)*Nn + s*256;
        u64 acc[16];
        #pragma unroll
        for (int h = 0; h < 16; h++) acc[h] = 0ull;

        #pragma unroll 2
        for (int step = 0; step < 8; step++) {
            int n0 = step*32 + nq*4;
            float4 xv = *(const float4*)(xrow + n0);
            u64 xp0 = pk2(xv.x, xv.y), xp1 = pk2(xv.z, xv.w);
            #pragma unroll
            for (int h = 0; h < 16; h++) {
                ulonglong2 e2 = *(const ulonglong2*)&ex_s[h][n0];
                fma2(acc[h], xp0, e2.x);
                fma2(acc[h], xp1, e2.y);
            }
        }
        float pv[16];
        #pragma unroll
        for (int h = 0; h < 16; h++) {
            float2 v2 = unpk(acc[h]);
            float sv = v2.x + v2.y;
            sv += __shfl_xor_sync(0xffffffffu, sv, 1);
            sv += __shfl_xor_sync(0xffffffffu, sv, 2);
            sv += __shfl_xor_sync(0xffffffffu, sv, 4);
            pv[h] = sv;
        }
        if (nq == 0) {
            float* dst = g_pooled + ((size_t)b*Cc + c)*NHn;
            redv4(dst +  0, pv[0],  pv[1],  pv[2],  pv[3]);
            redv4(dst +  4, pv[4],  pv[5],  pv[6],  pv[7]);
            redv4(dst +  8, pv[8],  pv[9],  pv[10], pv[11]);
            redv4(dst + 12, pv[12], pv[13], pv[14], pv[15]);
        }
    }
}

// ---------------- fused values + vm (4 nodes/block, same b) ----------------
// inv computed inline from g_S (no fin kernel).
__global__ void values_vm_kernel(const float* __restrict__ vw, const float* __restrict__ vb,
                                 const float* __restrict__ msg_w, const float* __restrict__ msg_b) {
    int n0 = blockIdx.x * 4;        // nodes n0..n0+3: b = n0>>4, h0 = n0&15
    int b = n0 >> 4, h0 = n0 & 15;
    int tid = threadIdx.x; // 256
    __shared__ __align__(16) float ps[4*Cc];
    __shared__ __align__(16) float vs[4*Ee];
    float i0 = 1.0f/g_S[b*48 + h0],     i1 = 1.0f/g_S[b*48 + h0 + 1];
    float i2 = 1.0f/g_S[b*48 + h0 + 2], i3 = 1.0f/g_S[b*48 + h0 + 3];
    for (int c = tid; c < Cc; c += 256) {
        float4 v = *(const float4*)(g_pooled + ((size_t)b*Cc + c)*NHn + h0);
        ps[0*Cc + c] = v.x*i0; ps[1*Cc + c] = v.y*i1; ps[2*Cc + c] = v.z*i2; ps[3*Cc + c] = v.w*i3;
    }
    __syncthreads();
    {
        int e = tid;
        float bias = vb[e];
        float acc[4];
        #pragma unroll
        for (int i = 0; i < 4; i++) acc[i] = bias;
        const float4* w4 = (const float4*)(vw + (size_t)e*Cc);
        #pragma unroll 2
        for (int c4 = 0; c4 < Cc/4; c4++) {
            float4 wv = w4[c4];
            #pragma unroll
            for (int i = 0; i < 4; i++) {
                float4 a = ((const float4*)(ps + i*Cc))[c4];
                acc[i] += wv.x*a.x + wv.y*a.y + wv.z*a.z + wv.w*a.w;
            }
        }
        #pragma unroll
        for (int i = 0; i < 4; i++) {
            vs[i*Ee + e] = acc[i];
            g_values[(size_t)(n0+i)*Ee + e] = acc[i];
        }
    }
    __syncthreads();
    for (int t = tid; t < 4*HIDn; t += 256) {
        int i = t >> 7, j = t & 127;
        float acc = msg_b[j];
        const float4* w4 = (const float4*)(msg_w + (size_t)j*Ee);
        const float4* v4 = (const float4*)(vs + i*Ee);
        #pragma unroll 4
        for (int k4 = 0; k4 < Ee/4; k4++) {
            float4 wv = w4[k4], a = v4[k4];
            acc += wv.x*a.x + wv.y*a.y + wv.z*a.z + wv.w*a.w;
        }
        g_vm[(size_t)(n0+i)*HIDn + j] = acc;
    }
}

// ---------------- edge kernel: RFF + gate + gather + segment mean ----------
// Positions computed inline from g_S (no fin / g_pos).
__global__ void edge_kernel(const int* __restrict__ esrc, const int* __restrict__ edst,
                            const float* __restrict__ brff, const float* __restrict__ embw,
                            int EG) {
    int e0  = blockIdx.x * 8;
    int tid = threadIdx.x; // 128
    __shared__ int   ssrc[8], sdst[8];
    __shared__ float srel[8][2];
    __shared__ __align__(16) float ea[8][64];

    if (tid < 8) {
        int idx = e0 + tid;
        int s_ = (idx < EG) ? esrc[idx] : 0;
        int d_ = (idx < EG) ? edst[idx] : 0;
        ssrc[tid] = s_; sdst[tid] = d_;
        int sb = s_ >> 4, sh = s_ & 15, db = d_ >> 4, dh = d_ & 15;
        float is = 1.0f/g_S[sb*48 + sh], id = 1.0f/g_S[db*48 + dh];
        srel[tid][0] = g_S[sb*48 + 16 + sh]*is - g_S[db*48 + 16 + dh]*id;
        srel[tid][1] = g_S[sb*48 + 32 + sh]*is - g_S[db*48 + 32 + dh]*id;
    }
    __syncthreads();
    if (tid < 32) {
        float b0 = brff[tid*2+0], b1 = brff[tid*2+1];
        #pragma unroll
        for (int e = 0; e < 8; e++) {
            float pj = srel[e][0]*b0 + srel[e][1]*b1;
            float sv, cv;
            __sincosf(pj, &sv, &cv);
            ea[e][tid]      = 1.41421356237f * sv;
            ea[e][tid + 32] = 1.41421356237f * cv;
        }
    }
    __syncthreads();

    float4 wr[16];
    const float4* wrow = (const float4*)(embw + (size_t)tid*64);
    #pragma unroll
    for (int i = 0; i < 16; i++) wr[i] = wrow[i];

    #pragma unroll
    for (int e = 0; e < 8; e++) {
        if (e0 + e >= EG) break;
        const float4* eav = (const float4*)ea[e];
        float g = 0.f;
        #pragma unroll
        for (int i = 0; i < 16; i++) {
            float4 a = eav[i];
            g += wr[i].x*a.x + wr[i].y*a.y + wr[i].z*a.z + wr[i].w*a.w;
        }
        float m = g_vm[(size_t)ssrc[e]*HIDn + tid] * g * (1.0f/15.0f);
        atomicAdd(&g_agg[(size_t)sdst[e]*HIDn + tid], m);
    }
}

// ---------------- final: silu MLP + layer scale + skip (4 nodes/block) -----
__global__ void final_kernel(const float* __restrict__ lin1_w, const float* __restrict__ lin1_b,
                             const float* __restrict__ lin2_w, const float* __restrict__ lin2_b,
                             const float* __restrict__ lscale, float* __restrict__ out) {
    int n0  = blockIdx.x * 4;
    int tid = threadIdx.x; // 256
    __shared__ __align__(16) float ag[4*HIDn];
    __shared__ __align__(16) float hs[4*512];
    for (int i = tid; i < 4*HIDn; i += 256) ag[i] = g_agg[(size_t)n0*HIDn + i];
    __syncthreads();

    for (int j = tid; j < 512; j += 256) {
        const float4* w4 = (const float4*)(lin1_w + (size_t)j*HIDn);
        float a0 = lin1_b[j], a1 = a0, a2 = a0, a3 = a0;
        const float4* g0 = (const float4*)(ag);
        const float4* g1 = (const float4*)(ag + HIDn);
        const float4* g2 = (const float4*)(ag + 2*HIDn);
        const float4* g3 = (const float4*)(ag + 3*HIDn);
        #pragma unroll 2
        for (int k4 = 0; k4 < HIDn/4; k4++) {
            float4 wv = w4[k4];
            float4 b0 = g0[k4], b1v = g1[k4], b2 = g2[k4], b3 = g3[k4];
            a0 += wv.x*b0.x + wv.y*b0.y + wv.z*b0.z + wv.w*b0.w;
            a1 += wv.x*b1v.x + wv.y*b1v.y + wv.z*b1v.z + wv.w*b1v.w;
            a2 += wv.x*b2.x + wv.y*b2.y + wv.z*b2.z + wv.w*b2.w;
            a3 += wv.x*b3.x + wv.y*b3.y + wv.z*b3.z + wv.w*b3.w;
        }
        hs[0*512 + j] = a0 / (1.f + __expf(-a0));
        hs[1*512 + j] = a1 / (1.f + __expf(-a1));
        hs[2*512 + j] = a2 / (1.f + __expf(-a2));
        hs[3*512 + j] = a3 / (1.f + __expf(-a3));
    }
    __syncthreads();

    int e = tid;
    const float4* w4 = (const float4*)(lin2_w + (size_t)e*512);
    float o0 = lin2_b[e], o1 = o0, o2 = o0, o3 = o0;
    const float4* h0 = (const float4*)(hs);
    const float4* h1 = (const float4*)(hs + 512);
    const float4* h2 = (const float4*)(hs + 1024);
    const float4* h3 = (const float4*)(hs + 1536);
    #pragma unroll 2
    for (int j4 = 0; j4 < 128; j4++) {
        float4 wv = w4[j4];
        float4 b0 = h0[j4], b1v = h1[j4], b2 = h2[j4], b3 = h3[j4];
        o0 += wv.x*b0.x + wv.y*b0.y + wv.z*b0.z + wv.w*b0.w;
        o1 += wv.x*b1v.x + wv.y*b1v.y + wv.z*b1v.z + wv.w*b1v.w;
        o2 += wv.x*b2.x + wv.y*b2.y + wv.z*b2.z + wv.w*b2.w;
        o3 += wv.x*b3.x + wv.y*b3.y + wv.z*b3.z + wv.w*b3.w;
    }
    float ls = lscale[e];
    out[(size_t)(n0+0)*Ee + e] = ls*o0 + g_values[(size_t)(n0+0)*Ee + e];
    out[(size_t)(n0+1)*Ee + e] = ls*o1 + g_values[(size_t)(n0+1)*Ee + e];
    out[(size_t)(n0+2)*Ee + e] = ls*o2 + g_values[(size_t)(n0+2)*Ee + e];
    out[(size_t)(n0+3)*Ee + e] = ls*o3 + g_values[(size_t)(n0+3)*Ee + e];
}

// ---------------------------------------------------------------------------
extern "C" void kernel_launch(void* const* d_in, const int* in_sizes, int n_in,
                              void* d_out, int out_size) {
    const float* x      = (const float*)d_in[0];
    const float* qw     = (const float*)d_in[1];
    const float* qb     = (const float*)d_in[2];
    const float* kw     = (const float*)d_in[3];
    const float* kb     = (const float*)d_in[4];
    const float* vw     = (const float*)d_in[5];
    const float* vb     = (const float*)d_in[6];
    const float* brff   = (const float*)d_in[7];
    const float* msg_w  = (const float*)d_in[8];
    const float* msg_b  = (const float*)d_in[9];
    const float* emb_w  = (const float*)d_in[10];
    const float* lin1_w = (const float*)d_in[11];
    const float* lin1_b = (const float*)d_in[12];
    const float* lin2_w = (const float*)d_in[13];
    const float* lin2_b = (const float*)d_in[14];
    const float* lsc    = (const float*)d_in[15];
    const int*   esrc   = (const int*)d_in[16];
    const int*   edst   = (const int*)d_in[17];
    int EG = in_sizes[16];
    float* out = (float*)d_out;

    zero_kernel     <<<256, 256>>>();
    mean_kernel     <<<dim3(Cc/8, Bsz), 256>>>(x);
    qq_kernel       <<<dim3(4, Bsz), Cc>>>(qw, qb, kw, kb);
    logits_kernel   <<<dim3(Nn/256, Bsz), 256>>>(x);
    pool_kernel     <<<dim3(4, 16, Bsz), 256>>>(x);
    values_vm_kernel<<<NODES/4, 256>>>(vw, vb, msg_w, msg_b);
    edge_kernel     <<<(EG + 7)/8, 128>>>(esrc, edst, brff, emb_w, EG);
    final_kernel    <<<NODES/4, 256>>>(lin1_w, lin1_b, lin2_w, lin2_b, lsc, out);
}